// round 13
// baseline (speedup 1.0000x reference)
#include <cuda_runtime.h>
#include <cuda_bf16.h>
#include <cstdint>

#define NU_MAX 200000
#define NI_MAX 20000
#define NE_MAX 1000000

// ---------------- scratch (device globals; no allocation allowed) -------------
__device__ float  g_user_x[NU_MAX * 32];
__device__ float  g_item_x[NI_MAX * 32];
__device__ float  g_xl1[NU_MAX * 128];
__device__ float  g_xr1[NI_MAX * 128];
__device__ float  g_xr2[NU_MAX * 128];
__device__ float  g_item2[NI_MAX * 128];
__device__ float  g_xl2[NI_MAX * 128];
__device__ int    g_deg[NI_MAX + NU_MAX];
__device__ int2   g_offcnt[NI_MAX + NU_MAX];
__device__ int    g_cur[NI_MAX + NU_MAX];
__device__ int    g_bsum[64];
__device__ int    g_oth1[NE_MAX];
__device__ int    g_oth2[NE_MAX];
__device__ float4 g_ea1[NE_MAX];
__device__ __align__(16) __nv_bfloat16 g_wpack[150000];

// packed-weight offsets (bf16 elements)
#define WP_C1WL 0
#define WP_C2WR 10240
#define WP_C1WR 20480
#define WP_C2WL 30720
#define WP_PW1  67584
#define WP_PW2  104448
#define WP_ULW  141312

// ================= helpers =================
__device__ __forceinline__ uint32_t smem_u32(const void* p) {
    uint32_t a;
    asm("{ .reg .u64 t; cvta.to.shared.u64 t, %1; cvt.u32.u64 %0, t; }" : "=r"(a) : "l"(p));
    return a;
}
__device__ __forceinline__ void ldm_x4(uint32_t* r, uint32_t addr) {
    asm volatile("ldmatrix.sync.aligned.m8n8.x4.shared.b16 {%0,%1,%2,%3}, [%4];"
                 : "=r"(r[0]), "=r"(r[1]), "=r"(r[2]), "=r"(r[3]) : "r"(addr));
}
__device__ __forceinline__ void mma_bf16(float* c, const uint32_t* a, uint32_t b0, uint32_t b1) {
    asm volatile("mma.sync.aligned.m16n8k16.row.col.f32.bf16.bf16.f32 "
                 "{%0,%1,%2,%3}, {%4,%5,%6,%7}, {%8,%9}, {%0,%1,%2,%3};"
                 : "+f"(c[0]), "+f"(c[1]), "+f"(c[2]), "+f"(c[3])
                 : "r"(a[0]), "r"(a[1]), "r"(a[2]), "r"(a[3]), "r"(b0), "r"(b1));
}
__device__ __forceinline__ uint32_t pack_bf(__nv_bfloat16 a, __nv_bfloat16 b) {
    return (uint32_t)__bfloat16_as_ushort(a) | ((uint32_t)__bfloat16_as_ushort(b) << 16);
}

// ---------------- weight prepack: fp32 W[K,NOUT] -> hi/lo bf16 tiles ----------
template<int K, int NOUT, int CHUNK, int KP, int NCH>
__device__ __forceinline__ void prep_one(const float* __restrict__ W,
                                         __nv_bfloat16* __restrict__ dst, int i)
{
    constexpr int TOT = NCH * 2 * NOUT * KP;
    if (i >= TOT) return;
    int ch = i / (2 * NOUT * KP);
    int r = i - ch * (2 * NOUT * KP);
    int half = r / (NOUT * KP);
    int q = r - half * (NOUT * KP);
    int n = q / KP;
    int kloc = q - n * KP;
    int k = ch * CHUNK + kloc;
    float v = (kloc < CHUNK && k < K) ? W[k * NOUT + n] : 0.f;
    __nv_bfloat16 hi = __float2bfloat16(v);
    dst[i] = half ? __float2bfloat16(v - __bfloat162float(hi)) : hi;
}

__global__ void prepack_kernel(const float* w0, const float* w1, const float* w2,
                               const float* w3, const float* w4, const float* w5,
                               const float* w6, __nv_bfloat16* dst)
{
    int i = blockIdx.x * 256 + threadIdx.x;
    switch (blockIdx.y) {
    case 0: prep_one<32, 128, 32, 40, 1>(w0, dst + WP_C1WL, i); break;
    case 1: prep_one<32, 128, 32, 40, 1>(w1, dst + WP_C2WR, i); break;
    case 2: prep_one<32, 128, 32, 40, 1>(w2, dst + WP_C1WR, i); break;
    case 3: prep_one<128, 128, 64, 72, 2>(w3, dst + WP_C2WL, i); break;
    case 4: prep_one<128, 128, 64, 72, 2>(w4, dst + WP_PW1, i); break;
    case 5: prep_one<128, 128, 64, 72, 2>(w5, dst + WP_PW2, i); break;
    case 6: prep_one<101, 32, 112, 120, 1>(w6, dst + WP_ULW, i); break;
    }
}

// ---- shared device subroutines for HMMA blocks ----
template<int K, int CHUNK, int KP>
__device__ __forceinline__ void fill_A(const float* __restrict__ gin, int nrow_blk,
                                       __nv_bfloat16* sAh, __nv_bfloat16* sAl, int tid)
{
    constexpr int QPR = CHUNK / 4;
    for (int q = tid; q < 128 * QPR; q += 256) {
        int r = q / QPR;
        int c4 = (q - r * QPR) * 4;
        float4 v = (r < nrow_blk) ? *(const float4*)(gin + (size_t)r * K + c4)
                                  : make_float4(0.f, 0.f, 0.f, 0.f);
        __nv_bfloat16 h0 = __float2bfloat16(v.x), h1 = __float2bfloat16(v.y);
        __nv_bfloat16 h2 = __float2bfloat16(v.z), h3 = __float2bfloat16(v.w);
        __nv_bfloat16 l0 = __float2bfloat16(v.x - __bfloat162float(h0));
        __nv_bfloat16 l1 = __float2bfloat16(v.y - __bfloat162float(h1));
        __nv_bfloat16 l2 = __float2bfloat16(v.z - __bfloat162float(h2));
        __nv_bfloat16 l3 = __float2bfloat16(v.w - __bfloat162float(h3));
        uint32_t* ph = (uint32_t*)(sAh + r * KP + c4);
        uint32_t* pl = (uint32_t*)(sAl + r * KP + c4);
        ph[0] = pack_bf(h0, h1); ph[1] = pack_bf(h2, h3);
        pl[0] = pack_bf(l0, l1); pl[1] = pack_bf(l2, l3);
    }
}

template<int KP, int NB>
__device__ __forceinline__ void mma_chunk(float c[][4], uint32_t sAh0, uint32_t sAl0,
                                          uint32_t sBh0, uint32_t sBl0,
                                          uint32_t offA, int lrow, int lcol, int ksteps)
{
    for (int s = 0; s < ksteps; s++) {
        uint32_t ah[4], al[4];
        ldm_x4(ah, sAh0 + offA + s * 32);
        ldm_x4(al, sAl0 + offA + s * 32);
#pragma unroll
        for (int nbp = 0; nbp < NB; nbp++) {
            uint32_t offB = (uint32_t)((nbp * 16 + lrow) * KP + lcol) * 2 + s * 32;
            uint32_t bh[4], bl[4];
            ldm_x4(bh, sBh0 + offB);
            ldm_x4(bl, sBl0 + offB);
            mma_bf16(c[2 * nbp],     ah, bh[0], bh[2]);
            mma_bf16(c[2 * nbp],     ah, bl[0], bl[2]);
            mma_bf16(c[2 * nbp],     al, bh[0], bh[2]);
            mma_bf16(c[2 * nbp + 1], ah, bh[1], bh[3]);
            mma_bf16(c[2 * nbp + 1], ah, bl[1], bl[3]);
            mma_bf16(c[2 * nbp + 1], al, bh[1], bh[3]);
        }
    }
}

// ---------------- HMMA GEMM: out[nrows,128] = in[nrows,K] @ W[K,128] + b ------
template<int K>
__global__ void __launch_bounds__(256, 2) mma_gemm(
    const float* __restrict__ in, const __nv_bfloat16* __restrict__ Wp,
    const float* __restrict__ bias, float* __restrict__ out,
    int nrows, int do_relu)
{
    constexpr int CHUNK = (K < 64) ? K : 64;
    constexpr int NCH = K / CHUNK;
    constexpr int KP = CHUNK + 8;
    constexpr int TILE = 128 * KP;

    extern __shared__ __nv_bfloat16 smbf[];
    __nv_bfloat16* sAh = smbf;
    __nv_bfloat16* sAl = sAh + TILE;
    __nv_bfloat16* sBh = sAl + TILE;
    __shared__ float s_bias[128];

    const int tid = threadIdx.x;
    const int rowbase = blockIdx.x * 128;
    if (tid < 128) s_bias[tid] = bias[tid];
    int nrow_blk = nrows - rowbase; if (nrow_blk > 128) nrow_blk = 128;

    const int wid = tid >> 5;
    const int lane = tid & 31;
    const int m0 = wid * 16;
    const int lrow = lane & 15;
    const int lcol = (lane >> 4) << 3;

    float c[16][4];
#pragma unroll
    for (int nb = 0; nb < 16; nb++)
#pragma unroll
        for (int q = 0; q < 4; q++) c[nb][q] = 0.f;

    const uint32_t sAh0 = smem_u32(sAh), sAl0 = smem_u32(sAl);
    const uint32_t sBh0 = smem_u32(sBh), sBl0 = sBh0 + TILE * 2;
    const uint32_t offA = (uint32_t)((m0 + lrow) * KP + lcol) * 2;

#pragma unroll
    for (int ch = 0; ch < NCH; ch++) {
        if (ch) __syncthreads();
        fill_A<K, CHUNK, KP>(in + (size_t)rowbase * K + ch * CHUNK, nrow_blk, sAh, sAl, tid);
        {
            const uint4* bsrc = (const uint4*)(Wp + (size_t)ch * 2 * TILE);
            uint4* bdst = (uint4*)sBh;
            for (int i = tid; i < (2 * TILE) / 8; i += 256) bdst[i] = bsrc[i];
        }
        __syncthreads();
        mma_chunk<KP, 8>(c, sAh0, sAl0, sBh0, sBl0, offA, lrow, lcol, CHUNK / 16);
    }

    const int r0 = rowbase + m0 + (lane >> 2);
    const int r1 = r0 + 8;
    const int cb = (lane & 3) * 2;
#pragma unroll
    for (int nb = 0; nb < 16; nb++) {
        int col = nb * 8 + cb;
        float2 v0, v1;
        v0.x = c[nb][0] + s_bias[col];
        v0.y = c[nb][1] + s_bias[col + 1];
        v1.x = c[nb][2] + s_bias[col];
        v1.y = c[nb][3] + s_bias[col + 1];
        if (do_relu) {
            v0.x = fmaxf(v0.x, 0.f); v0.y = fmaxf(v0.y, 0.f);
            v1.x = fmaxf(v1.x, 0.f); v1.y = fmaxf(v1.y, 0.f);
        }
        if (r0 < nrows) *(float2*)(out + (size_t)r0 * 128 + col) = v0;
        if (r1 < nrows) *(float2*)(out + (size_t)r1 * 128 + col) = v1;
    }
}

// ---------------- fused 2-layer MLP: z = relu(in@W1+b1)@W2+b2 ----------------
__global__ void __launch_bounds__(256, 2) mlp_fused(
    const float* __restrict__ in,
    const __nv_bfloat16* __restrict__ W1p, const float* __restrict__ b1,
    const __nv_bfloat16* __restrict__ W2p, const float* __restrict__ b2,
    float* __restrict__ z, int nrows)
{
    constexpr int K = 128, CHUNK = 64, KP = 72, TILE = 128 * KP;
    extern __shared__ __nv_bfloat16 smbf[];
    __nv_bfloat16* sAh = smbf;
    __nv_bfloat16* sAl = sAh + TILE;
    __nv_bfloat16* sBh = sAl + TILE;          // stage1 B (hi+lo)
    __nv_bfloat16* sB2 = smbf + 4 * TILE;     // stage2 B (hi+lo)
    __shared__ float s_b1[128], s_b2[128];

    const int tid = threadIdx.x;
    const int rowbase = blockIdx.x * 128;
    if (tid < 128) { s_b1[tid] = b1[tid]; s_b2[tid] = b2[tid]; }
    int nrow_blk = nrows - rowbase; if (nrow_blk > 128) nrow_blk = 128;

    const int wid = tid >> 5;
    const int lane = tid & 31;
    const int m0 = wid * 16;
    const int lrow = lane & 15;
    const int lcol = (lane >> 4) << 3;

    float c[16][4];
#pragma unroll
    for (int nb = 0; nb < 16; nb++)
#pragma unroll
        for (int q = 0; q < 4; q++) c[nb][q] = 0.f;

    const uint32_t sAh0 = smem_u32(sAh), sAl0 = smem_u32(sAl);
    const uint32_t sBh0 = smem_u32(sBh), sBl0 = sBh0 + TILE * 2;
    const uint32_t sB2h0 = smem_u32(sB2), sB2l0 = sB2h0 + TILE * 2;
    const uint32_t offA = (uint32_t)((m0 + lrow) * KP + lcol) * 2;

    // prefetch stage-2 B chunk 0 into its (idle) region up front
    {
        const uint4* bsrc = (const uint4*)W2p;
        uint4* bdst = (uint4*)sB2;
        for (int i = tid; i < (2 * TILE) / 8; i += 256) bdst[i] = bsrc[i];
    }

    // ---- stage 1: hid = relu(in@W1 + b1) ----
#pragma unroll
    for (int ch = 0; ch < 2; ch++) {
        if (ch) __syncthreads();
        fill_A<K, CHUNK, KP>(in + (size_t)rowbase * K + ch * CHUNK, nrow_blk, sAh, sAl, tid);
        {
            const uint4* bsrc = (const uint4*)(W1p + (size_t)ch * 2 * TILE);
            uint4* bdst = (uint4*)sBh;
            for (int i = tid; i < (2 * TILE) / 8; i += 256) bdst[i] = bsrc[i];
        }
        __syncthreads();
        mma_chunk<KP, 8>(c, sAh0, sAl0, sBh0, sBl0, offA, lrow, lcol, 4);
    }
    __syncthreads();

    // ---- convert hid rows to hi/lo bf16 H tiles ----
    {
        const int rr0 = m0 + (lane >> 2);
        const int rr1 = rr0 + 8;
        const int cb = (lane & 3) * 2;
#pragma unroll
        for (int nb = 0; nb < 16; nb++) {
            int col = nb * 8 + cb;
            int ch = col >> 6;
            int kloc = col & 63;
            float v0 = fmaxf(c[nb][0] + s_b1[col], 0.f);
            float v1 = fmaxf(c[nb][1] + s_b1[col + 1], 0.f);
            float v2 = fmaxf(c[nb][2] + s_b1[col], 0.f);
            float v3 = fmaxf(c[nb][3] + s_b1[col + 1], 0.f);
            __nv_bfloat16 h0 = __float2bfloat16(v0), h1 = __float2bfloat16(v1);
            __nv_bfloat16 h2 = __float2bfloat16(v2), h3 = __float2bfloat16(v3);
            __nv_bfloat16 l0 = __float2bfloat16(v0 - __bfloat162float(h0));
            __nv_bfloat16 l1 = __float2bfloat16(v1 - __bfloat162float(h1));
            __nv_bfloat16 l2 = __float2bfloat16(v2 - __bfloat162float(h2));
            __nv_bfloat16 l3 = __float2bfloat16(v3 - __bfloat162float(h3));
            __nv_bfloat16* Hh = smbf + ch * 2 * TILE;
            __nv_bfloat16* Hl = Hh + TILE;
            *(uint32_t*)(Hh + rr0 * KP + kloc) = pack_bf(h0, h1);
            *(uint32_t*)(Hl + rr0 * KP + kloc) = pack_bf(l0, l1);
            *(uint32_t*)(Hh + rr1 * KP + kloc) = pack_bf(h2, h3);
            *(uint32_t*)(Hl + rr1 * KP + kloc) = pack_bf(l2, l3);
        }
    }
    __syncthreads();

    // ---- stage 2: z = hid@W2 + b2 ----
#pragma unroll
    for (int nb = 0; nb < 16; nb++)
#pragma unroll
        for (int q = 0; q < 4; q++) c[nb][q] = 0.f;

#pragma unroll
    for (int ch = 0; ch < 2; ch++) {
        if (ch) {
            __syncthreads();
            const uint4* bsrc = (const uint4*)(W2p + (size_t)2 * TILE);
            uint4* bdst = (uint4*)sB2;
            for (int i = tid; i < (2 * TILE) / 8; i += 256) bdst[i] = bsrc[i];
            __syncthreads();
        }
        uint32_t Hh0 = smem_u32(smbf + ch * 2 * TILE);
        uint32_t Hl0 = Hh0 + TILE * 2;
        mma_chunk<KP, 8>(c, Hh0, Hl0, sB2h0, sB2l0, offA, lrow, lcol, 4);
    }

    const int r0 = rowbase + m0 + (lane >> 2);
    const int r1 = r0 + 8;
    const int cb = (lane & 3) * 2;
#pragma unroll
    for (int nb = 0; nb < 16; nb++) {
        int col = nb * 8 + cb;
        float2 v0, v1;
        v0.x = c[nb][0] + s_b2[col];
        v0.y = c[nb][1] + s_b2[col + 1];
        v1.x = c[nb][2] + s_b2[col];
        v1.y = c[nb][3] + s_b2[col + 1];
        if (r0 < nrows) *(float2*)(z + (size_t)r0 * 128 + col) = v0;
        if (r1 < nrows) *(float2*)(z + (size_t)r1 * 128 + col) = v1;
    }
}

// ---------------- HMMA user linear: out[nrows,32] = in[nrows,101] @ W + b -----
__global__ void __launch_bounds__(256, 2) mma_gemm101(
    const float* __restrict__ in, const __nv_bfloat16* __restrict__ Wp,
    const float* __restrict__ bias, float* __restrict__ out, int nrows)
{
    constexpr int K = 101;
    constexpr int KP = 120;
    constexpr int TILEA = 128 * KP;
    constexpr int TILEB = 32 * KP;

    extern __shared__ __nv_bfloat16 smbf[];
    __nv_bfloat16* sAh = smbf;
    __nv_bfloat16* sAl = sAh + TILEA;
    __nv_bfloat16* sBh = sAl + TILEA;
    __shared__ float s_bias[32];

    const int tid = threadIdx.x;
    const int rowbase = blockIdx.x * 128;
    if (tid < 32) s_bias[tid] = bias[tid];
    int nrow_blk = nrows - rowbase; if (nrow_blk > 128) nrow_blk = 128;

    {
        uint4* zz = (uint4*)sAh;
        for (int i = tid; i < (2 * TILEA) / 8; i += 256) zz[i] = make_uint4(0, 0, 0, 0);
    }
    __syncthreads();
    {
        const uint4* bsrc = (const uint4*)Wp;
        uint4* bdst = (uint4*)sBh;
        for (int i = tid; i < (2 * TILEB) / 8; i += 256) bdst[i] = bsrc[i];
    }
    const float* gin = in + (size_t)rowbase * K;
    if (rowbase + 128 <= nrows) {
        for (int q = tid; q < (128 * K) / 4; q += 256) {
            float4 v = ((const float4*)gin)[q];
            int f = q * 4;
            float vv[4] = {v.x, v.y, v.z, v.w};
#pragma unroll
            for (int e = 0; e < 4; e++) {
                int idx = f + e;
                int r = idx / K;
                int cc = idx - r * K;
                __nv_bfloat16 hi = __float2bfloat16(vv[e]);
                __nv_bfloat16 lo = __float2bfloat16(vv[e] - __bfloat162float(hi));
                sAh[r * KP + cc] = hi;
                sAl[r * KP + cc] = lo;
            }
        }
    } else {
        for (int i = tid; i < 128 * K; i += 256) {
            int r = i / K;
            int cc = i - r * K;
            float x = (r < nrow_blk) ? gin[i] : 0.f;
            __nv_bfloat16 hi = __float2bfloat16(x);
            __nv_bfloat16 lo = __float2bfloat16(x - __bfloat162float(hi));
            sAh[r * KP + cc] = hi;
            sAl[r * KP + cc] = lo;
        }
    }
    __syncthreads();

    const int wid = tid >> 5;
    const int lane = tid & 31;
    const int m0 = wid * 16;
    const int lrow = lane & 15;
    const int lcol = (lane >> 4) << 3;

    float c[4][4];
#pragma unroll
    for (int nb = 0; nb < 4; nb++)
#pragma unroll
        for (int q = 0; q < 4; q++) c[nb][q] = 0.f;

    const uint32_t sAh0 = smem_u32(sAh), sAl0 = smem_u32(sAl);
    const uint32_t sBh0 = smem_u32(sBh), sBl0 = sBh0 + TILEB * 2;
    const uint32_t offA = (uint32_t)((m0 + lrow) * KP + lcol) * 2;

#pragma unroll
    for (int s = 0; s < 7; s++) {
        uint32_t ah[4], al[4];
        ldm_x4(ah, sAh0 + offA + s * 32);
        ldm_x4(al, sAl0 + offA + s * 32);
#pragma unroll
        for (int nbp = 0; nbp < 2; nbp++) {
            uint32_t offB = (uint32_t)((nbp * 16 + lrow) * KP + lcol) * 2 + s * 32;
            uint32_t bh[4], bl[4];
            ldm_x4(bh, sBh0 + offB);
            ldm_x4(bl, sBl0 + offB);
            mma_bf16(c[2 * nbp],     ah, bh[0], bh[2]);
            mma_bf16(c[2 * nbp],     ah, bl[0], bl[2]);
            mma_bf16(c[2 * nbp],     al, bh[0], bh[2]);
            mma_bf16(c[2 * nbp + 1], ah, bh[1], bh[3]);
            mma_bf16(c[2 * nbp + 1], ah, bl[1], bl[3]);
            mma_bf16(c[2 * nbp + 1], al, bh[1], bh[3]);
        }
    }

    const int r0 = rowbase + m0 + (lane >> 2);
    const int r1 = r0 + 8;
    const int cb = (lane & 3) * 2;
#pragma unroll
    for (int nb = 0; nb < 4; nb++) {
        int col = nb * 8 + cb;
        float2 v0, v1;
        v0.x = c[nb][0] + s_bias[col];
        v0.y = c[nb][1] + s_bias[col + 1];
        v1.x = c[nb][2] + s_bias[col];
        v1.y = c[nb][3] + s_bias[col + 1];
        if (r0 < nrows) *(float2*)(out + (size_t)r0 * 32 + col) = v0;
        if (r1 < nrows) *(float2*)(out + (size_t)r1 * 32 + col) = v1;
    }
}

// ---------------- trivial item linear ----------------
__global__ void item_lin_kernel(const float* __restrict__ fx, const float* __restrict__ w,
                                const float* __restrict__ b, float* __restrict__ out, int ni)
{
    int i = blockIdx.x * blockDim.x + threadIdx.x;
    if (i < ni * 32) {
        int r = i >> 5, c = i & 31;
        out[i] = fmaf(fx[r], w[c], b[c]);
    }
}

// ---------------- CSR build ----------------
__global__ void count_kernel(const int* __restrict__ src, const int* __restrict__ dst,
                             int* __restrict__ c1, int* __restrict__ c2, int E)
{
    int i = blockIdx.x * blockDim.x + threadIdx.x;
    if (i < E) {
        atomicAdd(&c1[dst[i]], 1);
        atomicAdd(&c2[src[i]], 1);
    }
}

__global__ void scan_p1(const int* __restrict__ cnt, int* __restrict__ bsum, int ntot)
{
    __shared__ int wsum[32];
    int tid = threadIdx.x;
    int i0 = blockIdx.x * 4096 + tid * 4;
    int s = 0;
    if (i0 + 3 < ntot) {
        int4 v = *(const int4*)(cnt + i0);
        s = v.x + v.y + v.z + v.w;
    } else {
        for (int e = 0; e < 4 && i0 + e < ntot; e++) s += cnt[i0 + e];
    }
#pragma unroll
    for (int d = 16; d; d >>= 1) s += __shfl_xor_sync(0xffffffffu, s, d);
    if ((tid & 31) == 0) wsum[tid >> 5] = s;
    __syncthreads();
    if (tid < 32) {
        int w = wsum[tid];
#pragma unroll
        for (int d = 16; d; d >>= 1) w += __shfl_xor_sync(0xffffffffu, w, d);
        if (tid == 0) bsum[blockIdx.x] = w;
    }
}

__global__ void scan_p2(int* __restrict__ bsum, int nblk)
{
    int tid = threadIdx.x;   // 64 threads
    int v = (tid < nblk) ? bsum[tid] : 0;
    int x = v;
#pragma unroll
    for (int d = 1; d < 32; d <<= 1) {
        int y = __shfl_up_sync(0xffffffffu, x, d);
        if ((tid & 31) >= d) x += y;
    }
    __shared__ int w0;
    if (tid == 31) w0 = x;
    __syncthreads();
    int excl = x - v + ((tid >= 32) ? w0 : 0);
    if (tid < nblk) bsum[tid] = excl;
}

__global__ void scan_p3(const int* __restrict__ cnt, const int* __restrict__ bsum,
                        int2* __restrict__ offcnt, int* __restrict__ cur,
                        int ntot, int seg2_start, int E)
{
    __shared__ int wsum[32];
    int tid = threadIdx.x;
    int i0 = blockIdx.x * 4096 + tid * 4;
    int4 v = make_int4(0, 0, 0, 0);
    if (i0 + 3 < ntot) v = *(const int4*)(cnt + i0);
    else {
        if (i0 < ntot)     v.x = cnt[i0];
        if (i0 + 1 < ntot) v.y = cnt[i0 + 1];
        if (i0 + 2 < ntot) v.z = cnt[i0 + 2];
    }
    int tsum = v.x + v.y + v.z + v.w;
    int x = tsum;
#pragma unroll
    for (int d = 1; d < 32; d <<= 1) {
        int y = __shfl_up_sync(0xffffffffu, x, d);
        if ((tid & 31) >= d) x += y;
    }
    if ((tid & 31) == 31) wsum[tid >> 5] = x;
    __syncthreads();
    if (tid < 32) {
        int w = wsum[tid];
#pragma unroll
        for (int d = 1; d < 32; d <<= 1) {
            int y = __shfl_up_sync(0xffffffffu, w, d);
            if (tid >= d) w += y;
        }
        wsum[tid] = w;
    }
    __syncthreads();
    int wo = (tid >= 32) ? wsum[(tid >> 5) - 1] : 0;
    int excl = bsum[blockIdx.x] + wo + x - tsum;

    int e0 = excl, e1 = e0 + v.x, e2 = e1 + v.y, e3 = e2 + v.z;
    int off4[4] = {e0, e1, e2, e3};
    int cnt4[4] = {v.x, v.y, v.z, v.w};
#pragma unroll
    for (int e = 0; e < 4; e++) {
        int i = i0 + e;
        if (i < ntot) {
            int o = off4[e] - ((i >= seg2_start) ? E : 0);
            offcnt[i] = make_int2(o, cnt4[e]);
            cur[i] = o;
        }
    }
}

__global__ void scatter_kernel(const int* __restrict__ src, const int* __restrict__ dst,
                               const float* __restrict__ eattr,
                               int* __restrict__ cur1, int* __restrict__ cur2,
                               int* __restrict__ oth1, int* __restrict__ oth2,
                               float4* __restrict__ ea1, int E)
{
    int i = blockIdx.x * blockDim.x + threadIdx.x;
    if (i < E) {
        int s = src[i], d = dst[i];
        int p1 = atomicAdd(&cur1[d], 1);
        oth1[p1] = s;
        float a0 = eattr[(size_t)i * 3];
        float a1 = eattr[(size_t)i * 3 + 1];
        float a2 = eattr[(size_t)i * 3 + 2];
        ea1[p1] = make_float4(a0, a1, a2, 0.f);
        int p2 = atomicAdd(&cur2[s], 1);
        oth2[p2] = d;
    }
}

// ---------------- fused GATv2 conv: online softmax + aggregation --------------
struct Chain { float M, S; float4 A; };

__device__ __forceinline__ void chain_update(Chain& ch, float t, const float4& xs)
{
    float Mn = fmaxf(ch.M, t);
    float corr = __expf(ch.M - Mn);
    float p = __expf(t - Mn);
    ch.S = ch.S * corr + p;
    ch.A.x = fmaf(ch.A.x, corr, p * xs.x);
    ch.A.y = fmaf(ch.A.y, corr, p * xs.y);
    ch.A.z = fmaf(ch.A.z, corr, p * xs.z);
    ch.A.w = fmaf(ch.A.w, corr, p * xs.w);
    ch.M = Mn;
}

__global__ void gat_conv_kernel(
    const float* __restrict__ xl, const float* __restrict__ xr,
    const int2* __restrict__ offcnt,
    const int* __restrict__ other,
    const float4* __restrict__ ea,
    const float* __restrict__ we,
    const float* __restrict__ att,
    const float* __restrict__ bias, float* __restrict__ out,
    int n, int do_relu)
{
    __shared__ int    s_o[8][32];
    __shared__ float4 s_ea[8][32];

    const int lane = threadIdx.x & 31;
    const int wrp = threadIdx.x >> 5;
    const int node = blockIdx.x * 8 + wrp;
    if (node >= n) return;

    float4 att4 = ((const float4*)att)[lane];
    float4 bias4 = ((const float4*)bias)[lane];
    int2 oc = __ldg(offcnt + node);
    const int start = oc.x;
    const int m = oc.y;

    if (m == 0) {
        float4 o = bias4;
        if (do_relu) {
            o.x = fmaxf(o.x, 0.f); o.y = fmaxf(o.y, 0.f);
            o.z = fmaxf(o.z, 0.f); o.w = fmaxf(o.w, 0.f);
        }
        ((float4*)(out + (size_t)node * 128))[lane] = o;
        return;
    }

    float4 we0 = make_float4(0, 0, 0, 0), we1 = we0, we2 = we0;
    if (we) {
        we0 = ((const float4*)we)[lane];
        we1 = ((const float4*)(we + 128))[lane];
        we2 = ((const float4*)(we + 256))[lane];
    }
    float4 xr4 = __ldg((const float4*)(xr + (size_t)node * 128) + lane);

    const float NEGINF = __int_as_float(0xff800000u);
    Chain c0, c1;
    c0.M = NEGINF; c0.S = 0.f; c0.A = make_float4(0.f, 0.f, 0.f, 0.f);
    c1 = c0;

    for (int base = 0; base < m; base += 32) {
        int i = base + lane;
        if (i < m) {
            s_o[wrp][lane] = __ldg(other + start + i);
            if (ea) s_ea[wrp][lane] = __ldg(ea + start + i);
        }
        __syncwarp();
        int lim = m - base; if (lim > 32) lim = 32;

        // software pipeline: keep next gather in flight across current compute
        float4 xs = __ldg((const float4*)(xl + (size_t)s_o[wrp][0] * 128) + lane);
#pragma unroll 2
        for (int j = 0; j < lim; j++) {
            float4 xs_next;
            if (j + 1 < lim)
                xs_next = __ldg((const float4*)(xl + (size_t)s_o[wrp][j + 1] * 128) + lane);
            float4 m4;
            m4.x = xs.x + xr4.x; m4.y = xs.y + xr4.y;
            m4.z = xs.z + xr4.z; m4.w = xs.w + xr4.w;
            if (ea) {
                float4 e = s_ea[wrp][j];
                m4.x = fmaf(e.x, we0.x, fmaf(e.y, we1.x, fmaf(e.z, we2.x, m4.x)));
                m4.y = fmaf(e.x, we0.y, fmaf(e.y, we1.y, fmaf(e.z, we2.y, m4.y)));
                m4.z = fmaf(e.x, we0.z, fmaf(e.y, we1.z, fmaf(e.z, we2.z, m4.z)));
                m4.w = fmaf(e.x, we0.w, fmaf(e.y, we1.w, fmaf(e.z, we2.w, m4.w)));
            }
            float g0 = fmaxf(m4.x, 0.2f * m4.x);
            float g1 = fmaxf(m4.y, 0.2f * m4.y);
            float g2 = fmaxf(m4.z, 0.2f * m4.z);
            float g3 = fmaxf(m4.w, 0.2f * m4.w);
            float t = g0 * att4.x + g1 * att4.y + g2 * att4.z + g3 * att4.w;
            t += __shfl_xor_sync(0xffffffffu, t, 1);
            t += __shfl_xor_sync(0xffffffffu, t, 2);
            t += __shfl_xor_sync(0xffffffffu, t, 4);
            if (j & 1) chain_update(c1, t, xs);
            else       chain_update(c0, t, xs);
            xs = xs_next;
        }
        __syncwarp();
    }

    float Mn = fmaxf(c0.M, c1.M);
    float w0 = __expf(c0.M - Mn), w1 = __expf(c1.M - Mn);
    float ssum = c0.S * w0 + c1.S * w1;
    float4 a;
    a.x = c0.A.x * w0 + c1.A.x * w1;
    a.y = c0.A.y * w0 + c1.A.y * w1;
    a.z = c0.A.z * w0 + c1.A.z * w1;
    a.w = c0.A.w * w0 + c1.A.w * w1;

    float inv = 1.f / (ssum + 1e-16f);
    float4 o;
    o.x = fmaf(a.x, inv, bias4.x);
    o.y = fmaf(a.y, inv, bias4.y);
    o.z = fmaf(a.z, inv, bias4.z);
    o.w = fmaf(a.w, inv, bias4.w);
    if (do_relu) {
        o.x = fmaxf(o.x, 0.f); o.y = fmaxf(o.y, 0.f);
        o.z = fmaxf(o.z, 0.f); o.w = fmaxf(o.w, 0.f);
    }
    ((float4*)(out + (size_t)node * 128))[lane] = o;
}

// ---------------- host launch ----------------
extern "C" void kernel_launch(void* const* d_in, const int* in_sizes, int n_in,
                              void* d_out, int out_size)
{
    (void)n_in; (void)out_size;
    const float* customer_x = (const float*)d_in[0];
    const float* fund_x     = (const float*)d_in[1];
    const float* edge_attr  = (const float*)d_in[2];
    const float* user_lin_w = (const float*)d_in[3];
    const float* user_lin_b = (const float*)d_in[4];
    const float* item_lin_w = (const float*)d_in[5];
    const float* item_lin_b = (const float*)d_in[6];
    const float* conv1_wl   = (const float*)d_in[7];
    const float* conv1_bl   = (const float*)d_in[8];
    const float* conv1_wr   = (const float*)d_in[9];
    const float* conv1_br   = (const float*)d_in[10];
    const float* conv1_we   = (const float*)d_in[11];
    const float* conv1_att  = (const float*)d_in[12];
    const float* conv1_bias = (const float*)d_in[13];
    const float* conv2_wl   = (const float*)d_in[14];
    const float* conv2_bl   = (const float*)d_in[15];
    const float* conv2_wr   = (const float*)d_in[16];
    const float* conv2_br   = (const float*)d_in[17];
    const float* conv2_att  = (const float*)d_in[18];
    const float* conv2_bias = (const float*)d_in[19];
    const float* proj_w1    = (const float*)d_in[20];
    const float* proj_b1    = (const float*)d_in[21];
    const float* proj_w2    = (const float*)d_in[22];
    const float* proj_b2    = (const float*)d_in[23];
    const int*   edge_src   = (const int*)d_in[24];
    const int*   edge_dst   = (const int*)d_in[25];

    const int Nu = in_sizes[0] / 101;
    const int Ni = in_sizes[1];
    const int E  = in_sizes[24];

    float *user_x, *item_x, *xl1, *xr1, *xr2, *item2, *xl2;
    int *deg, *cur, *oth1, *oth2, *bsum;
    int2* offcnt;
    float4* ea1;
    __nv_bfloat16* wp;
    cudaGetSymbolAddress((void**)&user_x, g_user_x);
    cudaGetSymbolAddress((void**)&item_x, g_item_x);
    cudaGetSymbolAddress((void**)&xl1,    g_xl1);
    cudaGetSymbolAddress((void**)&xr1,    g_xr1);
    cudaGetSymbolAddress((void**)&xr2,    g_xr2);
    cudaGetSymbolAddress((void**)&item2,  g_item2);
    cudaGetSymbolAddress((void**)&xl2,    g_xl2);
    cudaGetSymbolAddress((void**)&deg,    g_deg);
    cudaGetSymbolAddress((void**)&offcnt, g_offcnt);
    cudaGetSymbolAddress((void**)&cur,    g_cur);
    cudaGetSymbolAddress((void**)&bsum,   g_bsum);
    cudaGetSymbolAddress((void**)&oth1,   g_oth1);
    cudaGetSymbolAddress((void**)&oth2,   g_oth2);
    cudaGetSymbolAddress((void**)&ea1,    g_ea1);
    cudaGetSymbolAddress((void**)&wp,     g_wpack);

    int  *cnt1 = deg, *cnt2 = deg + NI_MAX;
    int2 *oc1 = offcnt, *oc2 = offcnt + NI_MAX;
    int  *cur1 = cur, *cur2 = cur + NI_MAX;

    const int smemMM32   = 4 * 128 * 40 * 2;                   // 40960
    const int smemMM128  = 4 * 128 * 72 * 2;                   // 73728
    const int smemMM101  = (2 * 128 * 120 + 2 * 32 * 120) * 2; // 76800
    const int smemFused  = 6 * 128 * 72 * 2;                   // 110592
    cudaFuncSetAttribute(mma_gemm<32>,   cudaFuncAttributeMaxDynamicSharedMemorySize, smemMM32);
    cudaFuncSetAttribute(mma_gemm<128>,  cudaFuncAttributeMaxDynamicSharedMemorySize, smemMM128);
    cudaFuncSetAttribute(mma_gemm101,    cudaFuncAttributeMaxDynamicSharedMemorySize, smemMM101);
    cudaFuncSetAttribute(mlp_fused,      cudaFuncAttributeMaxDynamicSharedMemorySize, smemFused);

    float* user_out = (float*)d_out;             // [Nu,128]
    float* z        = user_out + (size_t)Nu * 128;

    const int ntot = NI_MAX + Nu;
    const int nblk = (ntot + 4095) / 4096;

    // ONE side stream (two streams tripped the teardown memory guard in R12).
    cudaStream_t s1;
    cudaStreamCreateWithFlags(&s1, cudaStreamNonBlocking);
    cudaEvent_t eFork, eUx, eJoin1, eJoin2;
    cudaEventCreateWithFlags(&eFork,  cudaEventDisableTiming);
    cudaEventCreateWithFlags(&eUx,    cudaEventDisableTiming);
    cudaEventCreateWithFlags(&eJoin1, cudaEventDisableTiming);
    cudaEventCreateWithFlags(&eJoin2, cudaEventDisableTiming);

    // main: weight prepack
    prepack_kernel<<<dim3(144, 7), 256>>>(conv1_wl, conv2_wr, conv1_wr,
                                          conv2_wl, proj_w1, proj_w2,
                                          user_lin_w, wp);
    cudaEventRecord(eFork, 0);
    cudaStreamWaitEvent(s1, eFork, 0);

    // side s1: CSR build + item-side projections
    cudaMemsetAsync(deg, 0, (size_t)ntot * sizeof(int), s1);
    count_kernel<<<(E + 255) / 256, 256, 0, s1>>>(edge_src, edge_dst, cnt1, cnt2, E);
    // main: user linear
    mma_gemm101<<<(Nu + 127) / 128, 256, smemMM101>>>(customer_x, wp + WP_ULW, user_lin_b, user_x, Nu);
    cudaEventRecord(eUx, 0);
    // side s1 continued
    scan_p1<<<nblk, 1024, 0, s1>>>(deg, bsum, ntot);
    scan_p2<<<1, 64, 0, s1>>>(bsum, nblk);
    scan_p3<<<nblk, 1024, 0, s1>>>(deg, bsum, offcnt, cur, ntot, NI_MAX, E);
    scatter_kernel<<<(E + 255) / 256, 256, 0, s1>>>(edge_src, edge_dst, edge_attr,
                                                    cur1, cur2, oth1, oth2, ea1, E);
    item_lin_kernel<<<(Ni * 32 + 255) / 256, 256, 0, s1>>>(fund_x, item_lin_w, item_lin_b, item_x, Ni);
    mma_gemm<32><<<(Ni + 127) / 128, 256, smemMM32, s1>>>(item_x, wp + WP_C1WR, conv1_br, xr1, Ni, 0);
    cudaEventRecord(eJoin1, s1);
    // side s1: xr2 (needs user_x) — overlaps gat1 on main
    cudaStreamWaitEvent(s1, eUx, 0);
    mma_gemm<32><<<(Nu + 127) / 128, 256, smemMM32, s1>>>(user_x, wp + WP_C2WR, conv2_br, xr2, Nu, 0);
    cudaEventRecord(eJoin2, s1);

    // main: xl1 projection
    mma_gemm<32><<<(Nu + 127) / 128, 256, smemMM32>>>(user_x, wp + WP_C1WL, conv1_bl, xl1, Nu, 0);

    // join CSR + xr1 before conv1
    cudaStreamWaitEvent(0, eJoin1, 0);
    gat_conv_kernel<<<(Ni + 7) / 8, 256>>>(xl1, xr1, oc1, oth1, ea1, conv1_we,
                                           conv1_att, conv1_bias, item2, Ni, 1);
    // conv2 projection of item2
    mma_gemm<128><<<(Ni + 127) / 128, 256, smemMM128>>>(item2, wp + WP_C2WL, conv2_bl, xl2, Ni, 0);
    // join xr2 before conv2 aggregation
    cudaStreamWaitEvent(0, eJoin2, 0);
    gat_conv_kernel<<<(Nu + 7) / 8, 256>>>(xl2, xr2, oc2, oth2, nullptr, nullptr,
                                           conv2_att, conv2_bias, user_out, Nu, 0);
    // final MLP (fused)
    mlp_fused<<<(Nu + 127) / 128, 256, smemFused>>>(user_out, wp + WP_PW1, proj_b1,
                                                    wp + WP_PW2, proj_b2, z, Nu);
}

// round 15
// speedup vs baseline: 1.0187x; 1.0187x over previous
#include <cuda_runtime.h>
#include <cuda_bf16.h>
#include <cstdint>

#define NU_MAX 200000
#define NI_MAX 20000
#define NE_MAX 1000000

// ---------------- scratch (device globals; no allocation allowed) -------------
__device__ float  g_user_x[NU_MAX * 32];
__device__ float  g_item_x[NI_MAX * 32];
__device__ float  g_xl1[NU_MAX * 128];
__device__ float  g_xr1[NI_MAX * 128];
__device__ float  g_xr2[NU_MAX * 128];
__device__ float  g_item2[NI_MAX * 128];
__device__ float  g_xl2[NI_MAX * 128];
__device__ int    g_deg[NI_MAX + NU_MAX];
__device__ int2   g_offcnt[NI_MAX + NU_MAX];
__device__ int    g_cur[NI_MAX + NU_MAX];
__device__ int    g_bsum[64];
__device__ int    g_oth1[NE_MAX];
__device__ int    g_oth2[NE_MAX];
__device__ float4 g_ea1[NE_MAX];
__device__ __align__(16) __nv_bfloat16 g_wpack[150000];

// packed-weight offsets (bf16 elements)
#define WP_C1WL 0
#define WP_C2WR 10240
#define WP_C1WR 20480
#define WP_C2WL 30720
#define WP_PW1  67584
#define WP_PW2  104448
#define WP_ULW  141312

// ================= helpers =================
__device__ __forceinline__ uint32_t smem_u32(const void* p) {
    uint32_t a;
    asm("{ .reg .u64 t; cvta.to.shared.u64 t, %1; cvt.u32.u64 %0, t; }" : "=r"(a) : "l"(p));
    return a;
}
__device__ __forceinline__ void ldm_x4(uint32_t* r, uint32_t addr) {
    asm volatile("ldmatrix.sync.aligned.m8n8.x4.shared.b16 {%0,%1,%2,%3}, [%4];"
                 : "=r"(r[0]), "=r"(r[1]), "=r"(r[2]), "=r"(r[3]) : "r"(addr));
}
__device__ __forceinline__ void mma_bf16(float* c, const uint32_t* a, uint32_t b0, uint32_t b1) {
    asm volatile("mma.sync.aligned.m16n8k16.row.col.f32.bf16.bf16.f32 "
                 "{%0,%1,%2,%3}, {%4,%5,%6,%7}, {%8,%9}, {%0,%1,%2,%3};"
                 : "+f"(c[0]), "+f"(c[1]), "+f"(c[2]), "+f"(c[3])
                 : "r"(a[0]), "r"(a[1]), "r"(a[2]), "r"(a[3]), "r"(b0), "r"(b1));
}
__device__ __forceinline__ uint32_t pack_bf(__nv_bfloat16 a, __nv_bfloat16 b) {
    return (uint32_t)__bfloat16_as_ushort(a) | ((uint32_t)__bfloat16_as_ushort(b) << 16);
}

// ---------------- weight prepack: fp32 W[K,NOUT] -> hi/lo bf16 tiles ----------
template<int K, int NOUT, int CHUNK, int KP, int NCH>
__device__ __forceinline__ void prep_one(const float* __restrict__ W,
                                         __nv_bfloat16* __restrict__ dst, int i)
{
    constexpr int TOT = NCH * 2 * NOUT * KP;
    if (i >= TOT) return;
    int ch = i / (2 * NOUT * KP);
    int r = i - ch * (2 * NOUT * KP);
    int half = r / (NOUT * KP);
    int q = r - half * (NOUT * KP);
    int n = q / KP;
    int kloc = q - n * KP;
    int k = ch * CHUNK + kloc;
    float v = (kloc < CHUNK && k < K) ? W[k * NOUT + n] : 0.f;
    __nv_bfloat16 hi = __float2bfloat16(v);
    dst[i] = half ? __float2bfloat16(v - __bfloat162float(hi)) : hi;
}

__global__ void prepack_kernel(const float* w0, const float* w1, const float* w2,
                               const float* w3, const float* w4, const float* w5,
                               const float* w6, __nv_bfloat16* dst)
{
    int i = blockIdx.x * 256 + threadIdx.x;
    switch (blockIdx.y) {
    case 0: prep_one<32, 128, 32, 40, 1>(w0, dst + WP_C1WL, i); break;
    case 1: prep_one<32, 128, 32, 40, 1>(w1, dst + WP_C2WR, i); break;
    case 2: prep_one<32, 128, 32, 40, 1>(w2, dst + WP_C1WR, i); break;
    case 3: prep_one<128, 128, 64, 72, 2>(w3, dst + WP_C2WL, i); break;
    case 4: prep_one<128, 128, 64, 72, 2>(w4, dst + WP_PW1, i); break;
    case 5: prep_one<128, 128, 64, 72, 2>(w5, dst + WP_PW2, i); break;
    case 6: prep_one<101, 32, 112, 120, 1>(w6, dst + WP_ULW, i); break;
    }
}

// ---- shared device subroutines for HMMA blocks ----
template<int K, int CHUNK, int KP>
__device__ __forceinline__ void fill_A(const float* __restrict__ gin, int nrow_blk,
                                       __nv_bfloat16* sAh, __nv_bfloat16* sAl, int tid)
{
    constexpr int QPR = CHUNK / 4;
    for (int q = tid; q < 128 * QPR; q += 256) {
        int r = q / QPR;
        int c4 = (q - r * QPR) * 4;
        float4 v = (r < nrow_blk) ? *(const float4*)(gin + (size_t)r * K + c4)
                                  : make_float4(0.f, 0.f, 0.f, 0.f);
        __nv_bfloat16 h0 = __float2bfloat16(v.x), h1 = __float2bfloat16(v.y);
        __nv_bfloat16 h2 = __float2bfloat16(v.z), h3 = __float2bfloat16(v.w);
        __nv_bfloat16 l0 = __float2bfloat16(v.x - __bfloat162float(h0));
        __nv_bfloat16 l1 = __float2bfloat16(v.y - __bfloat162float(h1));
        __nv_bfloat16 l2 = __float2bfloat16(v.z - __bfloat162float(h2));
        __nv_bfloat16 l3 = __float2bfloat16(v.w - __bfloat162float(h3));
        uint32_t* ph = (uint32_t*)(sAh + r * KP + c4);
        uint32_t* pl = (uint32_t*)(sAl + r * KP + c4);
        ph[0] = pack_bf(h0, h1); ph[1] = pack_bf(h2, h3);
        pl[0] = pack_bf(l0, l1); pl[1] = pack_bf(l2, l3);
    }
}

template<int KP, int NB>
__device__ __forceinline__ void mma_chunk(float c[][4], uint32_t sAh0, uint32_t sAl0,
                                          uint32_t sBh0, uint32_t sBl0,
                                          uint32_t offA, int lrow, int lcol, int ksteps)
{
    for (int s = 0; s < ksteps; s++) {
        uint32_t ah[4], al[4];
        ldm_x4(ah, sAh0 + offA + s * 32);
        ldm_x4(al, sAl0 + offA + s * 32);
#pragma unroll
        for (int nbp = 0; nbp < NB; nbp++) {
            uint32_t offB = (uint32_t)((nbp * 16 + lrow) * KP + lcol) * 2 + s * 32;
            uint32_t bh[4], bl[4];
            ldm_x4(bh, sBh0 + offB);
            ldm_x4(bl, sBl0 + offB);
            mma_bf16(c[2 * nbp],     ah, bh[0], bh[2]);
            mma_bf16(c[2 * nbp],     ah, bl[0], bl[2]);
            mma_bf16(c[2 * nbp],     al, bh[0], bh[2]);
            mma_bf16(c[2 * nbp + 1], ah, bh[1], bh[3]);
            mma_bf16(c[2 * nbp + 1], ah, bl[1], bl[3]);
            mma_bf16(c[2 * nbp + 1], al, bh[1], bh[3]);
        }
    }
}

// ---------------- HMMA GEMM: out[nrows,128] = in[nrows,K] @ W[K,128] + b ------
template<int K>
__global__ void __launch_bounds__(256, 2) mma_gemm(
    const float* __restrict__ in, const __nv_bfloat16* __restrict__ Wp,
    const float* __restrict__ bias, float* __restrict__ out,
    int nrows, int do_relu)
{
    constexpr int CHUNK = (K < 64) ? K : 64;
    constexpr int NCH = K / CHUNK;
    constexpr int KP = CHUNK + 8;
    constexpr int TILE = 128 * KP;

    extern __shared__ __nv_bfloat16 smbf[];
    __nv_bfloat16* sAh = smbf;
    __nv_bfloat16* sAl = sAh + TILE;
    __nv_bfloat16* sBh = sAl + TILE;
    __shared__ float s_bias[128];

    const int tid = threadIdx.x;
    const int rowbase = blockIdx.x * 128;
    if (tid < 128) s_bias[tid] = bias[tid];
    int nrow_blk = nrows - rowbase; if (nrow_blk > 128) nrow_blk = 128;

    const int wid = tid >> 5;
    const int lane = tid & 31;
    const int m0 = wid * 16;
    const int lrow = lane & 15;
    const int lcol = (lane >> 4) << 3;

    float c[16][4];
#pragma unroll
    for (int nb = 0; nb < 16; nb++)
#pragma unroll
        for (int q = 0; q < 4; q++) c[nb][q] = 0.f;

    const uint32_t sAh0 = smem_u32(sAh), sAl0 = smem_u32(sAl);
    const uint32_t sBh0 = smem_u32(sBh), sBl0 = sBh0 + TILE * 2;
    const uint32_t offA = (uint32_t)((m0 + lrow) * KP + lcol) * 2;

#pragma unroll
    for (int ch = 0; ch < NCH; ch++) {
        if (ch) __syncthreads();
        fill_A<K, CHUNK, KP>(in + (size_t)rowbase * K + ch * CHUNK, nrow_blk, sAh, sAl, tid);
        {
            const uint4* bsrc = (const uint4*)(Wp + (size_t)ch * 2 * TILE);
            uint4* bdst = (uint4*)sBh;
            for (int i = tid; i < (2 * TILE) / 8; i += 256) bdst[i] = bsrc[i];
        }
        __syncthreads();
        mma_chunk<KP, 8>(c, sAh0, sAl0, sBh0, sBl0, offA, lrow, lcol, CHUNK / 16);
    }

    const int r0 = rowbase + m0 + (lane >> 2);
    const int r1 = r0 + 8;
    const int cb = (lane & 3) * 2;
#pragma unroll
    for (int nb = 0; nb < 16; nb++) {
        int col = nb * 8 + cb;
        float2 v0, v1;
        v0.x = c[nb][0] + s_bias[col];
        v0.y = c[nb][1] + s_bias[col + 1];
        v1.x = c[nb][2] + s_bias[col];
        v1.y = c[nb][3] + s_bias[col + 1];
        if (do_relu) {
            v0.x = fmaxf(v0.x, 0.f); v0.y = fmaxf(v0.y, 0.f);
            v1.x = fmaxf(v1.x, 0.f); v1.y = fmaxf(v1.y, 0.f);
        }
        if (r0 < nrows) *(float2*)(out + (size_t)r0 * 128 + col) = v0;
        if (r1 < nrows) *(float2*)(out + (size_t)r1 * 128 + col) = v1;
    }
}

// ---------------- dual-output K=32 GEMM: shares A tile for two weights --------
__global__ void __launch_bounds__(256, 2) mma_gemm32_dual(
    const float* __restrict__ in,
    const __nv_bfloat16* __restrict__ Wp1, const float* __restrict__ b1, float* __restrict__ out1,
    const __nv_bfloat16* __restrict__ Wp2, const float* __restrict__ b2, float* __restrict__ out2,
    int nrows)
{
    constexpr int K = 32, KP = 40, TILE = 128 * KP;

    extern __shared__ __nv_bfloat16 smbf[];
    __nv_bfloat16* sAh = smbf;
    __nv_bfloat16* sAl = sAh + TILE;
    __nv_bfloat16* sBh = sAl + TILE;
    __shared__ float s_b1[128], s_b2[128];

    const int tid = threadIdx.x;
    const int rowbase = blockIdx.x * 128;
    if (tid < 128) { s_b1[tid] = b1[tid]; s_b2[tid] = b2[tid]; }
    int nrow_blk = nrows - rowbase; if (nrow_blk > 128) nrow_blk = 128;

    const int wid = tid >> 5;
    const int lane = tid & 31;
    const int m0 = wid * 16;
    const int lrow = lane & 15;
    const int lcol = (lane >> 4) << 3;

    const uint32_t sAh0 = smem_u32(sAh), sAl0 = smem_u32(sAl);
    const uint32_t sBh0 = smem_u32(sBh), sBl0 = sBh0 + TILE * 2;
    const uint32_t offA = (uint32_t)((m0 + lrow) * KP + lcol) * 2;

    fill_A<K, K, KP>(in + (size_t)rowbase * K, nrow_blk, sAh, sAl, tid);
    {
        const uint4* bsrc = (const uint4*)Wp1;
        uint4* bdst = (uint4*)sBh;
        for (int i = tid; i < (2 * TILE) / 8; i += 256) bdst[i] = bsrc[i];
    }
    __syncthreads();

    const int r0 = rowbase + m0 + (lane >> 2);
    const int r1 = r0 + 8;
    const int cb = (lane & 3) * 2;

    float c[16][4];
#pragma unroll
    for (int nb = 0; nb < 16; nb++)
#pragma unroll
        for (int q = 0; q < 4; q++) c[nb][q] = 0.f;
    mma_chunk<KP, 8>(c, sAh0, sAl0, sBh0, sBl0, offA, lrow, lcol, 2);

#pragma unroll
    for (int nb = 0; nb < 16; nb++) {
        int col = nb * 8 + cb;
        float2 v0, v1;
        v0.x = c[nb][0] + s_b1[col];
        v0.y = c[nb][1] + s_b1[col + 1];
        v1.x = c[nb][2] + s_b1[col];
        v1.y = c[nb][3] + s_b1[col + 1];
        if (r0 < nrows) *(float2*)(out1 + (size_t)r0 * 128 + col) = v0;
        if (r1 < nrows) *(float2*)(out1 + (size_t)r1 * 128 + col) = v1;
    }

    __syncthreads();   // B reads done before overwrite
    {
        const uint4* bsrc = (const uint4*)Wp2;
        uint4* bdst = (uint4*)sBh;
        for (int i = tid; i < (2 * TILE) / 8; i += 256) bdst[i] = bsrc[i];
    }
    __syncthreads();

#pragma unroll
    for (int nb = 0; nb < 16; nb++)
#pragma unroll
        for (int q = 0; q < 4; q++) c[nb][q] = 0.f;
    mma_chunk<KP, 8>(c, sAh0, sAl0, sBh0, sBl0, offA, lrow, lcol, 2);

#pragma unroll
    for (int nb = 0; nb < 16; nb++) {
        int col = nb * 8 + cb;
        float2 v0, v1;
        v0.x = c[nb][0] + s_b2[col];
        v0.y = c[nb][1] + s_b2[col + 1];
        v1.x = c[nb][2] + s_b2[col];
        v1.y = c[nb][3] + s_b2[col + 1];
        if (r0 < nrows) *(float2*)(out2 + (size_t)r0 * 128 + col) = v0;
        if (r1 < nrows) *(float2*)(out2 + (size_t)r1 * 128 + col) = v1;
    }
}

// ---------------- fused 2-layer MLP: z = relu(in@W1+b1)@W2+b2 ----------------
__global__ void __launch_bounds__(256, 2) mlp_fused(
    const float* __restrict__ in,
    const __nv_bfloat16* __restrict__ W1p, const float* __restrict__ b1,
    const __nv_bfloat16* __restrict__ W2p, const float* __restrict__ b2,
    float* __restrict__ z, int nrows)
{
    constexpr int K = 128, CHUNK = 64, KP = 72, TILE = 128 * KP;
    extern __shared__ __nv_bfloat16 smbf[];
    __nv_bfloat16* sAh = smbf;
    __nv_bfloat16* sAl = sAh + TILE;
    __nv_bfloat16* sBh = sAl + TILE;          // stage1 B (hi+lo)
    __nv_bfloat16* sB2 = smbf + 4 * TILE;     // stage2 B (hi+lo)
    __shared__ float s_b1[128], s_b2[128];

    const int tid = threadIdx.x;
    const int rowbase = blockIdx.x * 128;
    if (tid < 128) { s_b1[tid] = b1[tid]; s_b2[tid] = b2[tid]; }
    int nrow_blk = nrows - rowbase; if (nrow_blk > 128) nrow_blk = 128;

    const int wid = tid >> 5;
    const int lane = tid & 31;
    const int m0 = wid * 16;
    const int lrow = lane & 15;
    const int lcol = (lane >> 4) << 3;

    float c[16][4];
#pragma unroll
    for (int nb = 0; nb < 16; nb++)
#pragma unroll
        for (int q = 0; q < 4; q++) c[nb][q] = 0.f;

    const uint32_t sAh0 = smem_u32(sAh), sAl0 = smem_u32(sAl);
    const uint32_t sBh0 = smem_u32(sBh), sBl0 = sBh0 + TILE * 2;
    const uint32_t sB2h0 = smem_u32(sB2), sB2l0 = sB2h0 + TILE * 2;
    const uint32_t offA = (uint32_t)((m0 + lrow) * KP + lcol) * 2;

    // prefetch stage-2 B chunk 0 into its (idle) region up front
    {
        const uint4* bsrc = (const uint4*)W2p;
        uint4* bdst = (uint4*)sB2;
        for (int i = tid; i < (2 * TILE) / 8; i += 256) bdst[i] = bsrc[i];
    }

    // ---- stage 1: hid = relu(in@W1 + b1) ----
#pragma unroll
    for (int ch = 0; ch < 2; ch++) {
        if (ch) __syncthreads();
        fill_A<K, CHUNK, KP>(in + (size_t)rowbase * K + ch * CHUNK, nrow_blk, sAh, sAl, tid);
        {
            const uint4* bsrc = (const uint4*)(W1p + (size_t)ch * 2 * TILE);
            uint4* bdst = (uint4*)sBh;
            for (int i = tid; i < (2 * TILE) / 8; i += 256) bdst[i] = bsrc[i];
        }
        __syncthreads();
        mma_chunk<KP, 8>(c, sAh0, sAl0, sBh0, sBl0, offA, lrow, lcol, 4);
    }
    __syncthreads();   // all stage-1 smem reads done before H-tile overwrite

    // ---- convert hid rows (in registers) to hi/lo bf16 H tiles ----
    {
        const int rr0 = m0 + (lane >> 2);
        const int rr1 = rr0 + 8;
        const int cb = (lane & 3) * 2;
#pragma unroll
        for (int nb = 0; nb < 16; nb++) {
            int col = nb * 8 + cb;
            int ch = col >> 6;
            int kloc = col & 63;
            float v0 = fmaxf(c[nb][0] + s_b1[col], 0.f);
            float v1 = fmaxf(c[nb][1] + s_b1[col + 1], 0.f);
            float v2 = fmaxf(c[nb][2] + s_b1[col], 0.f);
            float v3 = fmaxf(c[nb][3] + s_b1[col + 1], 0.f);
            __nv_bfloat16 h0 = __float2bfloat16(v0), h1 = __float2bfloat16(v1);
            __nv_bfloat16 h2 = __float2bfloat16(v2), h3 = __float2bfloat16(v3);
            __nv_bfloat16 l0 = __float2bfloat16(v0 - __bfloat162float(h0));
            __nv_bfloat16 l1 = __float2bfloat16(v1 - __bfloat162float(h1));
            __nv_bfloat16 l2 = __float2bfloat16(v2 - __bfloat162float(h2));
            __nv_bfloat16 l3 = __float2bfloat16(v3 - __bfloat162float(h3));
            __nv_bfloat16* Hh = smbf + ch * 2 * TILE;
            __nv_bfloat16* Hl = Hh + TILE;
            *(uint32_t*)(Hh + rr0 * KP + kloc) = pack_bf(h0, h1);
            *(uint32_t*)(Hl + rr0 * KP + kloc) = pack_bf(l0, l1);
            *(uint32_t*)(Hh + rr1 * KP + kloc) = pack_bf(h2, h3);
            *(uint32_t*)(Hl + rr1 * KP + kloc) = pack_bf(l2, l3);
        }
    }
    __syncthreads();

    // ---- stage 2: z = hid@W2 + b2 ----
#pragma unroll
    for (int nb = 0; nb < 16; nb++)
#pragma unroll
        for (int q = 0; q < 4; q++) c[nb][q] = 0.f;

#pragma unroll
    for (int ch = 0; ch < 2; ch++) {
        if (ch) {
            __syncthreads();
            const uint4* bsrc = (const uint4*)(W2p + (size_t)2 * TILE);
            uint4* bdst = (uint4*)sB2;
            for (int i = tid; i < (2 * TILE) / 8; i += 256) bdst[i] = bsrc[i];
            __syncthreads();
        }
        uint32_t Hh0 = smem_u32(smbf + ch * 2 * TILE);
        uint32_t Hl0 = Hh0 + TILE * 2;
        mma_chunk<KP, 8>(c, Hh0, Hl0, sB2h0, sB2l0, offA, lrow, lcol, 4);
    }

    const int r0 = rowbase + m0 + (lane >> 2);
    const int r1 = r0 + 8;
    const int cb = (lane & 3) * 2;
#pragma unroll
    for (int nb = 0; nb < 16; nb++) {
        int col = nb * 8 + cb;
        float2 v0, v1;
        v0.x = c[nb][0] + s_b2[col];
        v0.y = c[nb][1] + s_b2[col + 1];
        v1.x = c[nb][2] + s_b2[col];
        v1.y = c[nb][3] + s_b2[col + 1];
        if (r0 < nrows) *(float2*)(z + (size_t)r0 * 128 + col) = v0;
        if (r1 < nrows) *(float2*)(z + (size_t)r1 * 128 + col) = v1;
    }
}

// ---------------- HMMA user linear: out[nrows,32] = in[nrows,101] @ W + b -----
__global__ void __launch_bounds__(256, 2) mma_gemm101(
    const float* __restrict__ in, const __nv_bfloat16* __restrict__ Wp,
    const float* __restrict__ bias, float* __restrict__ out, int nrows)
{
    constexpr int K = 101;
    constexpr int KP = 120;
    constexpr int TILEA = 128 * KP;
    constexpr int TILEB = 32 * KP;

    extern __shared__ __nv_bfloat16 smbf[];
    __nv_bfloat16* sAh = smbf;
    __nv_bfloat16* sAl = sAh + TILEA;
    __nv_bfloat16* sBh = sAl + TILEA;
    __shared__ float s_bias[32];

    const int tid = threadIdx.x;
    const int rowbase = blockIdx.x * 128;
    if (tid < 32) s_bias[tid] = bias[tid];
    int nrow_blk = nrows - rowbase; if (nrow_blk > 128) nrow_blk = 128;

    {
        uint4* zz = (uint4*)sAh;
        for (int i = tid; i < (2 * TILEA) / 8; i += 256) zz[i] = make_uint4(0, 0, 0, 0);
    }
    __syncthreads();
    {
        const uint4* bsrc = (const uint4*)Wp;
        uint4* bdst = (uint4*)sBh;
        for (int i = tid; i < (2 * TILEB) / 8; i += 256) bdst[i] = bsrc[i];
    }
    const float* gin = in + (size_t)rowbase * K;
    if (rowbase + 128 <= nrows) {
        for (int q = tid; q < (128 * K) / 4; q += 256) {
            float4 v = ((const float4*)gin)[q];
            int f = q * 4;
            float vv[4] = {v.x, v.y, v.z, v.w};
#pragma unroll
            for (int e = 0; e < 4; e++) {
                int idx = f + e;
                int r = idx / K;
                int cc = idx - r * K;
                __nv_bfloat16 hi = __float2bfloat16(vv[e]);
                __nv_bfloat16 lo = __float2bfloat16(vv[e] - __bfloat162float(hi));
                sAh[r * KP + cc] = hi;
                sAl[r * KP + cc] = lo;
            }
        }
    } else {
        for (int i = tid; i < 128 * K; i += 256) {
            int r = i / K;
            int cc = i - r * K;
            float x = (r < nrow_blk) ? gin[i] : 0.f;
            __nv_bfloat16 hi = __float2bfloat16(x);
            __nv_bfloat16 lo = __float2bfloat16(x - __bfloat162float(hi));
            sAh[r * KP + cc] = hi;
            sAl[r * KP + cc] = lo;
        }
    }
    __syncthreads();

    const int wid = tid >> 5;
    const int lane = tid & 31;
    const int m0 = wid * 16;
    const int lrow = lane & 15;
    const int lcol = (lane >> 4) << 3;

    float c[4][4];
#pragma unroll
    for (int nb = 0; nb < 4; nb++)
#pragma unroll
        for (int q = 0; q < 4; q++) c[nb][q] = 0.f;

    const uint32_t sAh0 = smem_u32(sAh), sAl0 = smem_u32(sAl);
    const uint32_t sBh0 = smem_u32(sBh), sBl0 = sBh0 + TILEB * 2;
    const uint32_t offA = (uint32_t)((m0 + lrow) * KP + lcol) * 2;

#pragma unroll
    for (int s = 0; s < 7; s++) {
        uint32_t ah[4], al[4];
        ldm_x4(ah, sAh0 + offA + s * 32);
        ldm_x4(al, sAl0 + offA + s * 32);
#pragma unroll
        for (int nbp = 0; nbp < 2; nbp++) {
            uint32_t offB = (uint32_t)((nbp * 16 + lrow) * KP + lcol) * 2 + s * 32;
            uint32_t bh[4], bl[4];
            ldm_x4(bh, sBh0 + offB);
            ldm_x4(bl, sBl0 + offB);
            mma_bf16(c[2 * nbp],     ah, bh[0], bh[2]);
            mma_bf16(c[2 * nbp],     ah, bl[0], bl[2]);
            mma_bf16(c[2 * nbp],     al, bh[0], bh[2]);
            mma_bf16(c[2 * nbp + 1], ah, bh[1], bh[3]);
            mma_bf16(c[2 * nbp + 1], ah, bl[1], bl[3]);
            mma_bf16(c[2 * nbp + 1], al, bh[1], bh[3]);
        }
    }

    const int r0 = rowbase + m0 + (lane >> 2);
    const int r1 = r0 + 8;
    const int cb = (lane & 3) * 2;
#pragma unroll
    for (int nb = 0; nb < 4; nb++) {
        int col = nb * 8 + cb;
        float2 v0, v1;
        v0.x = c[nb][0] + s_bias[col];
        v0.y = c[nb][1] + s_bias[col + 1];
        v1.x = c[nb][2] + s_bias[col];
        v1.y = c[nb][3] + s_bias[col + 1];
        if (r0 < nrows) *(float2*)(out + (size_t)r0 * 32 + col) = v0;
        if (r1 < nrows) *(float2*)(out + (size_t)r1 * 32 + col) = v1;
    }
}

// ---------------- trivial item linear ----------------
__global__ void item_lin_kernel(const float* __restrict__ fx, const float* __restrict__ w,
                                const float* __restrict__ b, float* __restrict__ out, int ni)
{
    int i = blockIdx.x * blockDim.x + threadIdx.x;
    if (i < ni * 32) {
        int r = i >> 5, c = i & 31;
        out[i] = fmaf(fx[r], w[c], b[c]);
    }
}

// ---------------- CSR build ----------------
__global__ void count_kernel(const int* __restrict__ src, const int* __restrict__ dst,
                             int* __restrict__ c1, int* __restrict__ c2, int E)
{
    int i = blockIdx.x * blockDim.x + threadIdx.x;
    if (i < E) {
        atomicAdd(&c1[dst[i]], 1);
        atomicAdd(&c2[src[i]], 1);
    }
}

__global__ void scan_p1(const int* __restrict__ cnt, int* __restrict__ bsum, int ntot)
{
    __shared__ int wsum[32];
    int tid = threadIdx.x;
    int i0 = blockIdx.x * 4096 + tid * 4;
    int s = 0;
    if (i0 + 3 < ntot) {
        int4 v = *(const int4*)(cnt + i0);
        s = v.x + v.y + v.z + v.w;
    } else {
        for (int e = 0; e < 4 && i0 + e < ntot; e++) s += cnt[i0 + e];
    }
#pragma unroll
    for (int d = 16; d; d >>= 1) s += __shfl_xor_sync(0xffffffffu, s, d);
    if ((tid & 31) == 0) wsum[tid >> 5] = s;
    __syncthreads();
    if (tid < 32) {
        int w = wsum[tid];
#pragma unroll
        for (int d = 16; d; d >>= 1) w += __shfl_xor_sync(0xffffffffu, w, d);
        if (tid == 0) bsum[blockIdx.x] = w;
    }
}

__global__ void scan_p2(int* __restrict__ bsum, int nblk)
{
    int tid = threadIdx.x;   // 64 threads
    int v = (tid < nblk) ? bsum[tid] : 0;
    int x = v;
#pragma unroll
    for (int d = 1; d < 32; d <<= 1) {
        int y = __shfl_up_sync(0xffffffffu, x, d);
        if ((tid & 31) >= d) x += y;
    }
    __shared__ int w0;
    if (tid == 31) w0 = x;
    __syncthreads();
    int excl = x - v + ((tid >= 32) ? w0 : 0);
    if (tid < nblk) bsum[tid] = excl;
}

__global__ void scan_p3(const int* __restrict__ cnt, const int* __restrict__ bsum,
                        int2* __restrict__ offcnt, int* __restrict__ cur,
                        int ntot, int seg2_start, int E)
{
    __shared__ int wsum[32];
    int tid = threadIdx.x;
    int i0 = blockIdx.x * 4096 + tid * 4;
    int4 v = make_int4(0, 0, 0, 0);
    if (i0 + 3 < ntot) v = *(const int4*)(cnt + i0);
    else {
        if (i0 < ntot)     v.x = cnt[i0];
        if (i0 + 1 < ntot) v.y = cnt[i0 + 1];
        if (i0 + 2 < ntot) v.z = cnt[i0 + 2];
    }
    int tsum = v.x + v.y + v.z + v.w;
    int x = tsum;
#pragma unroll
    for (int d = 1; d < 32; d <<= 1) {
        int y = __shfl_up_sync(0xffffffffu, x, d);
        if ((tid & 31) >= d) x += y;
    }
    if ((tid & 31) == 31) wsum[tid >> 5] = x;
    __syncthreads();
    if (tid < 32) {
        int w = wsum[tid];
#pragma unroll
        for (int d = 1; d < 32; d <<= 1) {
            int y = __shfl_up_sync(0xffffffffu, w, d);
            if (tid >= d) w += y;
        }
        wsum[tid] = w;
    }
    __syncthreads();
    int wo = (tid >= 32) ? wsum[(tid >> 5) - 1] : 0;
    int excl = bsum[blockIdx.x] + wo + x - tsum;

    int e0 = excl, e1 = e0 + v.x, e2 = e1 + v.y, e3 = e2 + v.z;
    int off4[4] = {e0, e1, e2, e3};
    int cnt4[4] = {v.x, v.y, v.z, v.w};
#pragma unroll
    for (int e = 0; e < 4; e++) {
        int i = i0 + e;
        if (i < ntot) {
            int o = off4[e] - ((i >= seg2_start) ? E : 0);
            offcnt[i] = make_int2(o, cnt4[e]);
            cur[i] = o;
        }
    }
}

__global__ void scatter_kernel(const int* __restrict__ src, const int* __restrict__ dst,
                               const float* __restrict__ eattr,
                               int* __restrict__ cur1, int* __restrict__ cur2,
                               int* __restrict__ oth1, int* __restrict__ oth2,
                               float4* __restrict__ ea1, int E)
{
    int i = blockIdx.x * blockDim.x + threadIdx.x;
    if (i < E) {
        int s = src[i], d = dst[i];
        int p1 = atomicAdd(&cur1[d], 1);
        oth1[p1] = s;
        float a0 = eattr[(size_t)i * 3];
        float a1 = eattr[(size_t)i * 3 + 1];
        float a2 = eattr[(size_t)i * 3 + 2];
        ea1[p1] = make_float4(a0, a1, a2, 0.f);
        int p2 = atomicAdd(&cur2[s], 1);
        oth2[p2] = d;
    }
}

// ---------------- fused GATv2 conv: online softmax + aggregation --------------
struct Chain { float M, S; float4 A; };

__device__ __forceinline__ void chain_update(Chain& ch, float t, const float4& xs)
{
    float Mn = fmaxf(ch.M, t);
    float corr = __expf(ch.M - Mn);
    float p = __expf(t - Mn);
    ch.S = ch.S * corr + p;
    ch.A.x = fmaf(ch.A.x, corr, p * xs.x);
    ch.A.y = fmaf(ch.A.y, corr, p * xs.y);
    ch.A.z = fmaf(ch.A.z, corr, p * xs.z);
    ch.A.w = fmaf(ch.A.w, corr, p * xs.w);
    ch.M = Mn;
}

__global__ void gat_conv_kernel(
    const float* __restrict__ xl, const float* __restrict__ xr,
    const int2* __restrict__ offcnt,
    const int* __restrict__ other,
    const float4* __restrict__ ea,
    const float* __restrict__ we,
    const float* __restrict__ att,
    const float* __restrict__ bias, float* __restrict__ out,
    int n, int do_relu)
{
    __shared__ int    s_o[8][32];
    __shared__ float4 s_ea[8][32];

    const int lane = threadIdx.x & 31;
    const int wrp = threadIdx.x >> 5;
    const int node = blockIdx.x * 8 + wrp;
    if (node >= n) return;

    float4 att4 = ((const float4*)att)[lane];
    float4 bias4 = ((const float4*)bias)[lane];
    int2 oc = __ldg(offcnt + node);
    const int start = oc.x;
    const int m = oc.y;

    if (m == 0) {
        float4 o = bias4;
        if (do_relu) {
            o.x = fmaxf(o.x, 0.f); o.y = fmaxf(o.y, 0.f);
            o.z = fmaxf(o.z, 0.f); o.w = fmaxf(o.w, 0.f);
        }
        ((float4*)(out + (size_t)node * 128))[lane] = o;
        return;
    }

    float4 we0 = make_float4(0, 0, 0, 0), we1 = we0, we2 = we0;
    if (we) {
        we0 = ((const float4*)we)[lane];
        we1 = ((const float4*)(we + 128))[lane];
        we2 = ((const float4*)(we + 256))[lane];
    }
    float4 xr4 = __ldg((const float4*)(xr + (size_t)node * 128) + lane);

    const float NEGINF = __int_as_float(0xff800000u);
    Chain c0, c1;
    c0.M = NEGINF; c0.S = 0.f; c0.A = make_float4(0.f, 0.f, 0.f, 0.f);
    c1 = c0;

    for (int base = 0; base < m; base += 32) {
        int i = base + lane;
        if (i < m) {
            s_o[wrp][lane] = __ldg(other + start + i);
            if (ea) s_ea[wrp][lane] = __ldg(ea + start + i);
        }
        __syncwarp();
        int lim = m - base; if (lim > 32) lim = 32;
        for (int j = 0; j < lim; j++) {
            int srcn = s_o[wrp][j];
            float4 xs = __ldg((const float4*)(xl + (size_t)srcn * 128) + lane);
            float4 m4;
            m4.x = xs.x + xr4.x; m4.y = xs.y + xr4.y;
            m4.z = xs.z + xr4.z; m4.w = xs.w + xr4.w;
            if (ea) {
                float4 e = s_ea[wrp][j];
                m4.x = fmaf(e.x, we0.x, fmaf(e.y, we1.x, fmaf(e.z, we2.x, m4.x)));
                m4.y = fmaf(e.x, we0.y, fmaf(e.y, we1.y, fmaf(e.z, we2.y, m4.y)));
                m4.z = fmaf(e.x, we0.z, fmaf(e.y, we1.z, fmaf(e.z, we2.z, m4.z)));
                m4.w = fmaf(e.x, we0.w, fmaf(e.y, we1.w, fmaf(e.z, we2.w, m4.w)));
            }
            float g0 = fmaxf(m4.x, 0.2f * m4.x);
            float g1 = fmaxf(m4.y, 0.2f * m4.y);
            float g2 = fmaxf(m4.z, 0.2f * m4.z);
            float g3 = fmaxf(m4.w, 0.2f * m4.w);
            float t = g0 * att4.x + g1 * att4.y + g2 * att4.z + g3 * att4.w;
            t += __shfl_xor_sync(0xffffffffu, t, 1);
            t += __shfl_xor_sync(0xffffffffu, t, 2);
            t += __shfl_xor_sync(0xffffffffu, t, 4);
            if (j & 1) chain_update(c1, t, xs);
            else       chain_update(c0, t, xs);
        }
        __syncwarp();
    }

    float Mn = fmaxf(c0.M, c1.M);
    float w0 = __expf(c0.M - Mn), w1 = __expf(c1.M - Mn);
    float ssum = c0.S * w0 + c1.S * w1;
    float4 a;
    a.x = c0.A.x * w0 + c1.A.x * w1;
    a.y = c0.A.y * w0 + c1.A.y * w1;
    a.z = c0.A.z * w0 + c1.A.z * w1;
    a.w = c0.A.w * w0 + c1.A.w * w1;

    float inv = 1.f / (ssum + 1e-16f);
    float4 o;
    o.x = fmaf(a.x, inv, bias4.x);
    o.y = fmaf(a.y, inv, bias4.y);
    o.z = fmaf(a.z, inv, bias4.z);
    o.w = fmaf(a.w, inv, bias4.w);
    if (do_relu) {
        o.x = fmaxf(o.x, 0.f); o.y = fmaxf(o.y, 0.f);
        o.z = fmaxf(o.z, 0.f); o.w = fmaxf(o.w, 0.f);
    }
    ((float4*)(out + (size_t)node * 128))[lane] = o;
}

// ---------------- host launch ----------------
extern "C" void kernel_launch(void* const* d_in, const int* in_sizes, int n_in,
                              void* d_out, int out_size)
{
    (void)n_in; (void)out_size;
    const float* customer_x = (const float*)d_in[0];
    const float* fund_x     = (const float*)d_in[1];
    const float* edge_attr  = (const float*)d_in[2];
    const float* user_lin_w = (const float*)d_in[3];
    const float* user_lin_b = (const float*)d_in[4];
    const float* item_lin_w = (const float*)d_in[5];
    const float* item_lin_b = (const float*)d_in[6];
    const float* conv1_wl   = (const float*)d_in[7];
    const float* conv1_bl   = (const float*)d_in[8];
    const float* conv1_wr   = (const float*)d_in[9];
    const float* conv1_br   = (const float*)d_in[10];
    const float* conv1_we   = (const float*)d_in[11];
    const float* conv1_att  = (const float*)d_in[12];
    const float* conv1_bias = (const float*)d_in[13];
    const float* conv2_wl   = (const float*)d_in[14];
    const float* conv2_bl   = (const float*)d_in[15];
    const float* conv2_wr   = (const float*)d_in[16];
    const float* conv2_br   = (const float*)d_in[17];
    const float* conv2_att  = (const float*)d_in[18];
    const float* conv2_bias = (const float*)d_in[19];
    const float* proj_w1    = (const float*)d_in[20];
    const float* proj_b1    = (const float*)d_in[21];
    const float* proj_w2    = (const float*)d_in[22];
    const float* proj_b2    = (const float*)d_in[23];
    const int*   edge_src   = (const int*)d_in[24];
    const int*   edge_dst   = (const int*)d_in[25];

    const int Nu = in_sizes[0] / 101;
    const int Ni = in_sizes[1];
    const int E  = in_sizes[24];

    float *user_x, *item_x, *xl1, *xr1, *xr2, *item2, *xl2;
    int *deg, *cur, *oth1, *oth2, *bsum;
    int2* offcnt;
    float4* ea1;
    __nv_bfloat16* wp;
    cudaGetSymbolAddress((void**)&user_x, g_user_x);
    cudaGetSymbolAddress((void**)&item_x, g_item_x);
    cudaGetSymbolAddress((void**)&xl1,    g_xl1);
    cudaGetSymbolAddress((void**)&xr1,    g_xr1);
    cudaGetSymbolAddress((void**)&xr2,    g_xr2);
    cudaGetSymbolAddress((void**)&item2,  g_item2);
    cudaGetSymbolAddress((void**)&xl2,    g_xl2);
    cudaGetSymbolAddress((void**)&deg,    g_deg);
    cudaGetSymbolAddress((void**)&offcnt, g_offcnt);
    cudaGetSymbolAddress((void**)&cur,    g_cur);
    cudaGetSymbolAddress((void**)&bsum,   g_bsum);
    cudaGetSymbolAddress((void**)&oth1,   g_oth1);
    cudaGetSymbolAddress((void**)&oth2,   g_oth2);
    cudaGetSymbolAddress((void**)&ea1,    g_ea1);
    cudaGetSymbolAddress((void**)&wp,     g_wpack);

    int  *cnt1 = deg, *cnt2 = deg + NI_MAX;
    int2 *oc1 = offcnt, *oc2 = offcnt + NI_MAX;
    int  *cur1 = cur, *cur2 = cur + NI_MAX;

    const int smemMM32   = 4 * 128 * 40 * 2;                   // 40960
    const int smemMM128  = 4 * 128 * 72 * 2;                   // 73728
    const int smemMM101  = (2 * 128 * 120 + 2 * 32 * 120) * 2; // 76800
    const int smemFused  = 6 * 128 * 72 * 2;                   // 110592
    cudaFuncSetAttribute(mma_gemm<32>,   cudaFuncAttributeMaxDynamicSharedMemorySize, smemMM32);
    cudaFuncSetAttribute(mma_gemm32_dual,cudaFuncAttributeMaxDynamicSharedMemorySize, smemMM32);
    cudaFuncSetAttribute(mma_gemm<128>,  cudaFuncAttributeMaxDynamicSharedMemorySize, smemMM128);
    cudaFuncSetAttribute(mma_gemm101,    cudaFuncAttributeMaxDynamicSharedMemorySize, smemMM101);
    cudaFuncSetAttribute(mlp_fused,      cudaFuncAttributeMaxDynamicSharedMemorySize, smemFused);

    float* user_out = (float*)d_out;             // [Nu,128]
    float* z        = user_out + (size_t)Nu * 128;

    const int ntot = NI_MAX + Nu;
    const int nblk = (ntot + 4095) / 4096;

    // ONE side stream (two streams tripped the teardown memory guard in R12).
    cudaStream_t s1;
    cudaStreamCreateWithFlags(&s1, cudaStreamNonBlocking);
    cudaEvent_t eFork, eJoin;
    cudaEventCreateWithFlags(&eFork, cudaEventDisableTiming);
    cudaEventCreateWithFlags(&eJoin, cudaEventDisableTiming);

    // main: weight prepack
    prepack_kernel<<<dim3(144, 7), 256>>>(conv1_wl, conv2_wr, conv1_wr,
                                          conv2_wl, proj_w1, proj_w2,
                                          user_lin_w, wp);
    cudaEventRecord(eFork, 0);
    cudaStreamWaitEvent(s1, eFork, 0);

    // side s1: CSR build + item-side pipeline (independent of main chain)
    cudaMemsetAsync(deg, 0, (size_t)ntot * sizeof(int), s1);
    count_kernel<<<(E + 255) / 256, 256, 0, s1>>>(edge_src, edge_dst, cnt1, cnt2, E);
    // main: user linear
    mma_gemm101<<<(Nu + 127) / 128, 256, smemMM101>>>(customer_x, wp + WP_ULW, user_lin_b, user_x, Nu);
    // side: hierarchical scan + scatter + item projections
    scan_p1<<<nblk, 1024, 0, s1>>>(deg, bsum, ntot);
    scan_p2<<<1, 64, 0, s1>>>(bsum, nblk);
    scan_p3<<<nblk, 1024, 0, s1>>>(deg, bsum, offcnt, cur, ntot, NI_MAX, E);
    scatter_kernel<<<(E + 255) / 256, 256, 0, s1>>>(edge_src, edge_dst, edge_attr,
                                                    cur1, cur2, oth1, oth2, ea1, E);
    item_lin_kernel<<<(Ni * 32 + 255) / 256, 256, 0, s1>>>(fund_x, item_lin_w, item_lin_b, item_x, Ni);
    mma_gemm<32><<<(Ni + 127) / 128, 256, smemMM32, s1>>>(item_x, wp + WP_C1WR, conv1_br, xr1, Ni, 0);
    cudaEventRecord(eJoin, s1);

    // main: dual projection (xl1 + xr2 share user_x A tiles)
    mma_gemm32_dual<<<(Nu + 127) / 128, 256, smemMM32>>>(user_x,
                                                         wp + WP_C1WL, conv1_bl, xl1,
                                                         wp + WP_C2WR, conv2_br, xr2, Nu);

    // join side (CSR + xr1) before conv1
    cudaStreamWaitEvent(0, eJoin, 0);
    gat_conv_kernel<<<(Ni + 7) / 8, 256>>>(xl1, xr1, oc1, oth1, ea1, conv1_we,
                                           conv1_att, conv1_bias, item2, Ni, 1);
    // conv2 projection of item2
    mma_gemm<128><<<(Ni + 127) / 128, 256, smemMM128>>>(item2, wp + WP_C2WL, conv2_bl, xl2, Ni, 0);
    gat_conv_kernel<<<(Nu + 7) / 8, 256>>>(xl2, xr2, oc2, oth2, nullptr, nullptr,
                                           conv2_att, conv2_bias, user_out, Nu, 0);
    // final MLP (fused, no hid round trip)
    mlp_fused<<<(Nu + 127) / 128, 256, smemFused>>>(user_out, wp + WP_PW1, proj_b1,
                                                    wp + WP_PW2, proj_b2, z, Nu);
}